// round 1
// baseline (speedup 1.0000x reference)
#include <cuda_runtime.h>

// g_U[j][k] = (Re U[k][j], Im U[k][j]) : column j of the fixed 16x16 unitary
// implementing all 6 layers of Rot gates + CNOT rings. Computed on-device from
// `weights` by prep_kernel (weights are a runtime input, so no host precompute).
__device__ float2 g_U[16][16];

__device__ __forceinline__ float2 cmul(float2 a, float2 b) {
    return make_float2(a.x * b.x - a.y * b.y, a.x * b.y + a.y * b.x);
}

// ---------------------------------------------------------------------------
// Prep: 16 threads, thread j propagates basis vector e_j through the 6 layers.
// ---------------------------------------------------------------------------
__global__ void prep_kernel(const float* __restrict__ wts) {
    int j = threadIdx.x;
    if (j >= 16) return;

    float2 v[16];
#pragma unroll
    for (int k = 0; k < 16; ++k) v[k] = make_float2(k == j ? 1.0f : 0.0f, 0.0f);

#pragma unroll
    for (int l = 0; l < 6; ++l) {
        // Rot(phi, theta, omega) on each wire (wire w = bit (3-w) of k)
#pragma unroll
        for (int w = 0; w < 4; ++w) {
            float ph = wts[(l * 4 + w) * 3 + 0];
            float th = wts[(l * 4 + w) * 3 + 1];
            float om = wts[(l * 4 + w) * 3 + 2];
            float st, ct; sincosf(0.5f * th, &st, &ct);
            float sa, ca; sincosf(0.5f * (ph + om), &sa, &ca);
            float sb, cb; sincosf(0.5f * (ph - om), &sb, &cb);
            // ep = (ca,-sa), em = (cb,-sb)
            float2 m00 = make_float2( ca * ct, -sa * ct);   //  ep*c
            float2 m01 = make_float2(-cb * st, -sb * st);   // -conj(em)*s
            float2 m10 = make_float2( cb * st, -sb * st);   //  em*s
            float2 m11 = make_float2( ca * ct,  sa * ct);   //  conj(ep)*c
            int mask = 8 >> w;
#pragma unroll
            for (int k0 = 0; k0 < 16; ++k0) {
                if (k0 & mask) continue;
                int k1 = k0 | mask;
                float2 a = v[k0], b = v[k1];
                float2 n0 = cmul(m00, a), t0 = cmul(m01, b);
                float2 n1 = cmul(m10, a), t1 = cmul(m11, b);
                v[k0] = make_float2(n0.x + t0.x, n0.y + t0.y);
                v[k1] = make_float2(n1.x + t1.x, n1.y + t1.y);
            }
        }
        // CNOT ring: control w, target (w+r)%4; state[k] <-> state[k^tmask]
        // for every k with control bit set (permutation is pairwise swap).
        int r = l % 3 + 1;
#pragma unroll
        for (int w = 0; w < 4; ++w) {
            int cmask = 8 >> w;
            int tmask = 8 >> ((w + r) & 3);
#pragma unroll
            for (int k = 0; k < 16; ++k) {
                if ((k & cmask) && !(k & tmask)) {
                    float2 tmp = v[k]; v[k] = v[k | tmask]; v[k | tmask] = tmp;
                }
            }
        }
    }

#pragma unroll
    for (int k = 0; k < 16; ++k) g_U[j][k] = v[k];
}

// ---------------------------------------------------------------------------
// Packed f32x2 helpers (Blackwell FFMA2 — only reachable via PTX).
// Lane0 = real, lane1 = imag.
// ---------------------------------------------------------------------------
__device__ __forceinline__ unsigned long long splat2(float v) {
    unsigned long long r;
    asm("mov.b64 %0, {%1, %1};" : "=l"(r) : "f"(v));
    return r;
}
__device__ __forceinline__ void ffma2(unsigned long long& acc,
                                      unsigned long long a, unsigned long long b) {
    asm("fma.rn.f32x2 %0, %1, %2, %0;" : "+l"(acc) : "l"(a), "l"(b));
}
__device__ __forceinline__ float2 unpack2(unsigned long long v) {
    float2 r;
    asm("mov.b64 {%0, %1}, %2;" : "=f"(r.x), "=f"(r.y) : "l"(v));
    return r;
}

// ---------------------------------------------------------------------------
// Main: 2 batch elements per thread; shared 16x16 complex matrix (2 KB),
// warp-uniform broadcast loads; 512 FFMA2 per thread.
// ---------------------------------------------------------------------------
__global__ __launch_bounds__(256, 2)
void qmain_kernel(const float4* __restrict__ x4, float4* __restrict__ out4, int half) {
    __shared__ float2 sU[16][16];
    int tid = threadIdx.x;
    ((float2*)sU)[tid] = ((const float2*)g_U)[tid];   // 256 threads -> 256 float2
    __syncthreads();

    int gtid = blockIdx.x * 256 + tid;
    int b0 = gtid;
    int b1 = gtid + half;
    if (b0 >= half) return;

    // --- build the two rank-1 product states s0[16], s1[16] ---
    float s0[16], s1[16];
    {
        float4 xa = x4[b0];
        float4 xb = x4[b1];
        float c[4], s[4];
        __sincosf(0.5f * xa.x, &s[0], &c[0]);
        __sincosf(0.5f * xa.y, &s[1], &c[1]);
        __sincosf(0.5f * xa.z, &s[2], &c[2]);
        __sincosf(0.5f * xa.w, &s[3], &c[3]);
        float t2[4], t3[8];
        t2[0] = c[0] * c[1]; t2[1] = c[0] * s[1]; t2[2] = s[0] * c[1]; t2[3] = s[0] * s[1];
#pragma unroll
        for (int i = 0; i < 4; ++i) { t3[2 * i] = t2[i] * c[2]; t3[2 * i + 1] = t2[i] * s[2]; }
#pragma unroll
        for (int i = 0; i < 8; ++i) { s0[2 * i] = t3[i] * c[3]; s0[2 * i + 1] = t3[i] * s[3]; }

        __sincosf(0.5f * xb.x, &s[0], &c[0]);
        __sincosf(0.5f * xb.y, &s[1], &c[1]);
        __sincosf(0.5f * xb.z, &s[2], &c[2]);
        __sincosf(0.5f * xb.w, &s[3], &c[3]);
        t2[0] = c[0] * c[1]; t2[1] = c[0] * s[1]; t2[2] = s[0] * c[1]; t2[3] = s[0] * s[1];
#pragma unroll
        for (int i = 0; i < 4; ++i) { t3[2 * i] = t2[i] * c[2]; t3[2 * i + 1] = t2[i] * s[2]; }
#pragma unroll
        for (int i = 0; i < 8; ++i) { s1[2 * i] = t3[i] * c[3]; s1[2 * i + 1] = t3[i] * s[3]; }
    }

    // --- complex matvec t = U s for both elements, packed (re,im) FFMA2 ---
    unsigned long long acc0[16], acc1[16];
#pragma unroll
    for (int k = 0; k < 16; ++k) { acc0[k] = 0ull; acc1[k] = 0ull; }

#pragma unroll
    for (int j = 0; j < 16; ++j) {
        unsigned long long sj0 = splat2(s0[j]);
        unsigned long long sj1 = splat2(s1[j]);
        const unsigned long long* row = (const unsigned long long*)(&sU[j][0]);
#pragma unroll
        for (int k = 0; k < 16; ++k) {
            unsigned long long m = row[k];       // broadcast LDS, reused twice
            ffma2(acc0[k], m, sj0);
            ffma2(acc1[k], m, sj1);
        }
    }

    // --- probabilities + Z-sign butterfly + store, per element ---
#pragma unroll
    for (int e = 0; e < 2; ++e) {
        const unsigned long long* acc = (e == 0) ? acc0 : acc1;
        float p[16];
#pragma unroll
        for (int k = 0; k < 16; ++k) {
            float2 v = unpack2(acc[k]);
            p[k] = v.x * v.x + v.y * v.y;
        }
        float a8[8], a4[4];
        float q3 = 0.0f, q2 = 0.0f;
#pragma unroll
        for (int i = 0; i < 8; ++i) { a8[i] = p[2 * i] + p[2 * i + 1]; q3 += p[2 * i] - p[2 * i + 1]; }
#pragma unroll
        for (int i = 0; i < 4; ++i) { a4[i] = a8[2 * i] + a8[2 * i + 1]; q2 += a8[2 * i] - a8[2 * i + 1]; }
        float q1 = (a4[0] - a4[1]) + (a4[2] - a4[3]);
        float q0 = (a4[0] + a4[1]) - (a4[2] + a4[3]);
        out4[e == 0 ? b0 : b1] = make_float4(q0, q1, q2, q3);
    }
}

extern "C" void kernel_launch(void* const* d_in, const int* in_sizes, int n_in,
                              void* d_out, int out_size) {
    const float* x   = (const float*)d_in[0];
    const float* wts = (const float*)d_in[1];
    int nx = in_sizes[0];
    // safety: metadata order should be (x, weights); swap if sizes say otherwise
    if (n_in >= 2 && in_sizes[0] == 72 && in_sizes[1] != 72) {
        wts = (const float*)d_in[0];
        x   = (const float*)d_in[1];
        nx  = in_sizes[1];
    }
    int B = nx / 4;              // batch size (262144)
    int half = B / 2;            // threads total (2 elems/thread)
    int grid = (half + 255) / 256;

    prep_kernel<<<1, 32>>>(wts);
    qmain_kernel<<<grid, 256>>>((const float4*)x, (float4*)d_out, half);
}

// round 2
// speedup vs baseline: 2.4659x; 2.4659x over previous
#include <cuda_runtime.h>

// g_U[j][k] = (Re U[k][j], Im U[k][j]) : column j of the fixed 16x16 unitary
// implementing all 6 layers of Rot gates + CNOT rings.
__device__ __align__(16) float2 g_U[16][16];

__device__ __forceinline__ float2 cmul(float2 a, float2 b) {
    return make_float2(a.x * b.x - a.y * b.y, a.x * b.y + a.y * b.x);
}

// ---------------------------------------------------------------------------
// Prep: 512 threads. Threads 0..23 build the 24 gate matrices (precise
// sincosf) into shared. Then warp j (0..15) propagates basis vector e_j:
// lane k holds amplitude U[k][j]; 1-qubit gates via shfl_xor butterflies,
// CNOT permutations via computed-source shuffles. ~500-cycle critical path.
// ---------------------------------------------------------------------------
__global__ void prep_kernel(const float* __restrict__ wts) {
    __shared__ float2 sm[24][4];   // m00, m01, m10, m11 per gate
    int tid = threadIdx.x;
    if (tid < 24) {
        float ph = wts[tid * 3 + 0];
        float th = wts[tid * 3 + 1];
        float om = wts[tid * 3 + 2];
        float st, ct; sincosf(0.5f * th, &st, &ct);
        float sa, ca; sincosf(0.5f * (ph + om), &sa, &ca);
        float sb, cb; sincosf(0.5f * (ph - om), &sb, &cb);
        sm[tid][0] = make_float2( ca * ct, -sa * ct);   //  ep*c
        sm[tid][1] = make_float2(-cb * st, -sb * st);   // -conj(em)*s
        sm[tid][2] = make_float2( cb * st, -sb * st);   //  em*s
        sm[tid][3] = make_float2( ca * ct,  sa * ct);   //  conj(ep)*c
    }
    __syncthreads();

    int j    = tid >> 5;        // warp = column index
    int lane = tid & 31;
    int k    = lane & 15;       // amplitude index (halves of warp mirror)
    float2 v = make_float2(k == j ? 1.0f : 0.0f, 0.0f);

#pragma unroll
    for (int l = 0; l < 6; ++l) {
#pragma unroll
        for (int w = 0; w < 4; ++w) {
            int g = l * 4 + w;
            float2 m00 = sm[g][0], m01 = sm[g][1], m10 = sm[g][2], m11 = sm[g][3];
            int mask = 8 >> w;
            float px = __shfl_xor_sync(0xffffffffu, v.x, mask);
            float py = __shfl_xor_sync(0xffffffffu, v.y, mask);
            float2 p = make_float2(px, py);
            // bit clear: v' = m00*v + m01*p ; bit set: v' = m11*v + m10*p
            float2 cv = (k & mask) ? m11 : m00;
            float2 cp = (k & mask) ? m10 : m01;
            float2 a = cmul(cv, v), b = cmul(cp, p);
            v = make_float2(a.x + b.x, a.y + b.y);
        }
        int r = l % 3 + 1;
#pragma unroll
        for (int w = 0; w < 4; ++w) {
            int cmask = 8 >> w;
            int tmask = 8 >> ((w + r) & 3);
            int src = (k & cmask) ? (k ^ tmask) : k;
            src |= (lane & 16);   // stay within mirrored half-warp
            float nx = __shfl_sync(0xffffffffu, v.x, src);
            float ny = __shfl_sync(0xffffffffu, v.y, src);
            v = make_float2(nx, ny);
        }
    }
    if (lane < 16) g_U[j][k] = v;
}

// ---------------------------------------------------------------------------
// Packed f32x2 helpers. Lane0 = real, lane1 = imag.
// ---------------------------------------------------------------------------
__device__ __forceinline__ unsigned long long splat2(float v) {
    unsigned long long r;
    asm("mov.b64 %0, {%1, %1};" : "=l"(r) : "f"(v));
    return r;
}
__device__ __forceinline__ void ffma2(unsigned long long& acc,
                                      unsigned long long a, unsigned long long b) {
    asm("fma.rn.f32x2 %0, %1, %2, %0;" : "+l"(acc) : "l"(a), "l"(b));
}
__device__ __forceinline__ float2 unpack2(unsigned long long v) {
    float2 r;
    asm("mov.b64 {%0, %1}, %2;" : "=f"(r.x), "=f"(r.y) : "l"(v));
    return r;
}

// ---------------------------------------------------------------------------
// Main: 2 batch elements/thread, k-loop split in two halves (8 live f32x2
// accs), LDS.128 matrix loads (2 complex entries per load), factored state
// (h[4] x l[4] products), per-half sign-butterfly epilogue.
// ---------------------------------------------------------------------------
__global__ __launch_bounds__(256, 3)
void qmain_kernel(const float4* __restrict__ x4, float4* __restrict__ out4, int half) {
    __shared__ float4 sU[16][8];  // sU[j][kk] = (Re U[2kk][j], Im, Re U[2kk+1][j], Im)
    int tid = threadIdx.x;
    if (tid < 128) ((float4*)sU)[tid] = ((const float4*)g_U)[tid];
    __syncthreads();

    int gtid = blockIdx.x * 256 + tid;
    if (gtid >= half) return;

    float4 xa = x4[gtid];
    float4 xb = x4[gtid + half];

    // Factored product state: s_j = h[j>>2] * l[j&3]
    // qubit0 -> bit3, qubit1 -> bit2 (high pair); qubit2 -> bit1, qubit3 -> bit0.
    float h0[4], l0[4], h1[4], l1[4];
    {
        float c0, s0, c1, s1, c2, s2, c3, s3;
        __sincosf(0.5f * xa.x, &s0, &c0);
        __sincosf(0.5f * xa.y, &s1, &c1);
        __sincosf(0.5f * xa.z, &s2, &c2);
        __sincosf(0.5f * xa.w, &s3, &c3);
        h0[0] = c0 * c1; h0[1] = c0 * s1; h0[2] = s0 * c1; h0[3] = s0 * s1;
        l0[0] = c2 * c3; l0[1] = c2 * s3; l0[2] = s2 * c3; l0[3] = s2 * s3;
        __sincosf(0.5f * xb.x, &s0, &c0);
        __sincosf(0.5f * xb.y, &s1, &c1);
        __sincosf(0.5f * xb.z, &s2, &c2);
        __sincosf(0.5f * xb.w, &s3, &c3);
        h1[0] = c0 * c1; h1[1] = c0 * s1; h1[2] = s0 * c1; h1[3] = s0 * s1;
        l1[0] = c2 * c3; l1[1] = c2 * s3; l1[2] = s2 * c3; l1[3] = s2 * s3;
    }

    float q0a = 0.f, q1a = 0.f, q2a = 0.f, q3a = 0.f;
    float q0b = 0.f, q1b = 0.f, q2b = 0.f, q3b = 0.f;

#pragma unroll
    for (int hp = 0; hp < 2; ++hp) {      // k half: k = hp*8 + kk, bit3 of k == hp
        unsigned long long acc0[8], acc1[8];
#pragma unroll
        for (int kk = 0; kk < 8; ++kk) { acc0[kk] = 0ull; acc1[kk] = 0ull; }

#pragma unroll
        for (int j = 0; j < 16; ++j) {
            unsigned long long sja = splat2(h0[j >> 2] * l0[j & 3]);
            unsigned long long sjb = splat2(h1[j >> 2] * l1[j & 3]);
            const ulonglong2* row = reinterpret_cast<const ulonglong2*>(&sU[j][hp * 4]);
#pragma unroll
            for (int kk = 0; kk < 4; ++kk) {
                ulonglong2 m = row[kk];            // LDS.128: 2 complex entries
                ffma2(acc0[2 * kk],     m.x, sja);
                ffma2(acc0[2 * kk + 1], m.y, sja);
                ffma2(acc1[2 * kk],     m.x, sjb);
                ffma2(acc1[2 * kk + 1], m.y, sjb);
            }
        }

        // epilogue for this half: p_kk -> partial signed sums
#pragma unroll
        for (int e = 0; e < 2; ++e) {
            const unsigned long long* acc = (e == 0) ? acc0 : acc1;
            float p[8];
#pragma unroll
            for (int kk = 0; kk < 8; ++kk) {
                float2 v = unpack2(acc[kk]);
                p[kk] = v.x * v.x + v.y * v.y;
            }
            float s01 = p[0] + p[1], d01 = p[0] - p[1];
            float s23 = p[2] + p[3], d23 = p[2] - p[3];
            float s45 = p[4] + p[5], d45 = p[4] - p[5];
            float s67 = p[6] + p[7], d67 = p[6] - p[7];
            float u = s01 + s23, v2 = s45 + s67;
            float A   = u + v2;                    // total prob of this half
            float q1c = u - v2;                    // bit2 signed
            float q2c = (s01 - s23) + (s45 - s67); // bit1 signed
            float q3c = (d01 + d23) + (d45 + d67); // bit0 signed
            float q0c = hp ? -A : A;               // bit3 = hp
            if (e == 0) { q0a += q0c; q1a += q1c; q2a += q2c; q3a += q3c; }
            else        { q0b += q0c; q1b += q1c; q2b += q2c; q3b += q3c; }
        }
    }

    out4[gtid]        = make_float4(q0a, q1a, q2a, q3a);
    out4[gtid + half] = make_float4(q0b, q1b, q2b, q3b);
}

extern "C" void kernel_launch(void* const* d_in, const int* in_sizes, int n_in,
                              void* d_out, int out_size) {
    const float* x   = (const float*)d_in[0];
    const float* wts = (const float*)d_in[1];
    int nx = in_sizes[0];
    if (n_in >= 2 && in_sizes[0] == 72 && in_sizes[1] != 72) {
        wts = (const float*)d_in[0];
        x   = (const float*)d_in[1];
        nx  = in_sizes[1];
    }
    int B = nx / 4;              // 262144
    int half = B / 2;            // 2 elems/thread
    int grid = (half + 255) / 256;

    prep_kernel<<<1, 512>>>(wts);
    qmain_kernel<<<grid, 256>>>((const float4*)x, (float4*)d_out, half);
}

// round 3
// speedup vs baseline: 2.4714x; 1.0022x over previous
#include <cuda_runtime.h>

// g_U[j][k] = (Re U[k][j], Im U[k][j]) : column j of the fixed 16x16 unitary
// implementing all 6 layers of Rot gates + CNOT rings.
__device__ __align__(16) float2 g_U[16][16];

__device__ __forceinline__ float2 cmul(float2 a, float2 b) {
    return make_float2(a.x * b.x - a.y * b.y, a.x * b.y + a.y * b.x);
}

// ---------------------------------------------------------------------------
// Prep: 512 threads. Threads 0..23 build the 24 gate matrices (precise
// sincosf) into shared. Then warp j (0..15) propagates basis vector e_j:
// lane k holds amplitude U[k][j]; 1-qubit gates via shfl_xor butterflies,
// CNOT permutations via computed-source shuffles.
// ---------------------------------------------------------------------------
__global__ void prep_kernel(const float* __restrict__ wts) {
    __shared__ float2 sm[24][4];   // m00, m01, m10, m11 per gate
    int tid = threadIdx.x;
    if (tid < 24) {
        float ph = wts[tid * 3 + 0];
        float th = wts[tid * 3 + 1];
        float om = wts[tid * 3 + 2];
        float st, ct; sincosf(0.5f * th, &st, &ct);
        float sa, ca; sincosf(0.5f * (ph + om), &sa, &ca);
        float sb, cb; sincosf(0.5f * (ph - om), &sb, &cb);
        sm[tid][0] = make_float2( ca * ct, -sa * ct);   //  ep*c
        sm[tid][1] = make_float2(-cb * st, -sb * st);   // -conj(em)*s
        sm[tid][2] = make_float2( cb * st, -sb * st);   //  em*s
        sm[tid][3] = make_float2( ca * ct,  sa * ct);   //  conj(ep)*c
    }
    __syncthreads();

    int j    = tid >> 5;        // warp = column index
    int lane = tid & 31;
    int k    = lane & 15;       // amplitude index (halves of warp mirror)
    float2 v = make_float2(k == j ? 1.0f : 0.0f, 0.0f);

#pragma unroll
    for (int l = 0; l < 6; ++l) {
#pragma unroll
        for (int w = 0; w < 4; ++w) {
            int g = l * 4 + w;
            float2 m00 = sm[g][0], m01 = sm[g][1], m10 = sm[g][2], m11 = sm[g][3];
            int mask = 8 >> w;
            float px = __shfl_xor_sync(0xffffffffu, v.x, mask);
            float py = __shfl_xor_sync(0xffffffffu, v.y, mask);
            float2 p = make_float2(px, py);
            float2 cv = (k & mask) ? m11 : m00;
            float2 cp = (k & mask) ? m10 : m01;
            float2 a = cmul(cv, v), b = cmul(cp, p);
            v = make_float2(a.x + b.x, a.y + b.y);
        }
        int r = l % 3 + 1;
#pragma unroll
        for (int w = 0; w < 4; ++w) {
            int cmask = 8 >> w;
            int tmask = 8 >> ((w + r) & 3);
            int src = (k & cmask) ? (k ^ tmask) : k;
            src |= (lane & 16);
            float nx = __shfl_sync(0xffffffffu, v.x, src);
            float ny = __shfl_sync(0xffffffffu, v.y, src);
            v = make_float2(nx, ny);
        }
    }
    if (lane < 16) g_U[j][k] = v;
}

// ---------------------------------------------------------------------------
// Packed f32x2 helpers. Lane0 = real, lane1 = imag.
// ---------------------------------------------------------------------------
__device__ __forceinline__ unsigned long long splat2(float v) {
    unsigned long long r;
    asm("mov.b64 %0, {%1, %1};" : "=l"(r) : "f"(v));
    return r;
}
__device__ __forceinline__ void ffma2(unsigned long long& acc,
                                      unsigned long long a, unsigned long long b) {
    asm("fma.rn.f32x2 %0, %1, %2, %0;" : "+l"(acc) : "l"(a), "l"(b));
}
__device__ __forceinline__ float2 unpack2(unsigned long long v) {
    float2 r;
    asm("mov.b64 {%0, %1}, %2;" : "=f"(r.x), "=f"(r.y) : "l"(v));
    return r;
}

// ---------------------------------------------------------------------------
// Main: 4 batch elements/thread (LDS amortized 4x), k-loop split in halves
// (32 live f32x2 accs), LDS.128 matrix loads, factored state (h[4] x l[4]),
// per-half sign-butterfly epilogue. PDL: prologue (x loads + sincos) overlaps
// the prep kernel; only the g_U read waits on it.
// ---------------------------------------------------------------------------
__global__ __launch_bounds__(128, 3)
void qmain_kernel(const float4* __restrict__ x4, float4* __restrict__ out4, int quarter) {
    __shared__ float4 sU[16][8];  // sU[j][kk] = (Re U[2kk][j], Im, Re U[2kk+1][j], Im)
    int tid = threadIdx.x;
    int gtid = blockIdx.x * 128 + tid;

    // ---- prologue: independent of g_U (overlaps prep via PDL) ----
    float h[4][4], l[4][4];
#pragma unroll
    for (int e = 0; e < 4; ++e) {
        float4 xa = x4[gtid + e * quarter];
        float c0, s0, c1, s1, c2, s2, c3, s3;
        __sincosf(0.5f * xa.x, &s0, &c0);
        __sincosf(0.5f * xa.y, &s1, &c1);
        __sincosf(0.5f * xa.z, &s2, &c2);
        __sincosf(0.5f * xa.w, &s3, &c3);
        h[e][0] = c0 * c1; h[e][1] = c0 * s1; h[e][2] = s0 * c1; h[e][3] = s0 * s1;
        l[e][0] = c2 * c3; l[e][1] = c2 * s3; l[e][2] = s2 * c3; l[e][3] = s2 * s3;
    }

    // ---- wait for prep, then stage the unitary ----
    cudaGridDependencySynchronize();
    ((float4*)sU)[tid] = ((const float4*)g_U)[tid];   // 128 threads -> 128 float4
    __syncthreads();

    float q[4][4];
#pragma unroll
    for (int e = 0; e < 4; ++e)
#pragma unroll
        for (int i = 0; i < 4; ++i) q[e][i] = 0.f;

#pragma unroll
    for (int hp = 0; hp < 2; ++hp) {      // k half: k = hp*8 + kk, bit3 of k == hp
        unsigned long long acc[4][8];
#pragma unroll
        for (int e = 0; e < 4; ++e)
#pragma unroll
            for (int kk = 0; kk < 8; ++kk) acc[e][kk] = 0ull;

#pragma unroll
        for (int j = 0; j < 16; ++j) {
            unsigned long long sj[4];
#pragma unroll
            for (int e = 0; e < 4; ++e) sj[e] = splat2(h[e][j >> 2] * l[e][j & 3]);
            const ulonglong2* row = reinterpret_cast<const ulonglong2*>(&sU[j][hp * 4]);
#pragma unroll
            for (int kk = 0; kk < 4; ++kk) {
                ulonglong2 m = row[kk];            // LDS.128: 2 complex entries
#pragma unroll
                for (int e = 0; e < 4; ++e) {
                    ffma2(acc[e][2 * kk],     m.x, sj[e]);
                    ffma2(acc[e][2 * kk + 1], m.y, sj[e]);
                }
            }
        }

        // epilogue for this half: p_kk -> partial signed sums
#pragma unroll
        for (int e = 0; e < 4; ++e) {
            float p[8];
#pragma unroll
            for (int kk = 0; kk < 8; ++kk) {
                float2 v = unpack2(acc[e][kk]);
                p[kk] = v.x * v.x + v.y * v.y;
            }
            float s01 = p[0] + p[1], d01 = p[0] - p[1];
            float s23 = p[2] + p[3], d23 = p[2] - p[3];
            float s45 = p[4] + p[5], d45 = p[4] - p[5];
            float s67 = p[6] + p[7], d67 = p[6] - p[7];
            float u = s01 + s23, v2 = s45 + s67;
            float A = u + v2;
            q[e][0] += hp ? -A : A;                  // bit3 = hp
            q[e][1] += u - v2;                       // bit2
            q[e][2] += (s01 - s23) + (s45 - s67);    // bit1
            q[e][3] += (d01 + d23) + (d45 + d67);    // bit0
        }
    }

#pragma unroll
    for (int e = 0; e < 4; ++e)
        out4[gtid + e * quarter] = make_float4(q[e][0], q[e][1], q[e][2], q[e][3]);
}

extern "C" void kernel_launch(void* const* d_in, const int* in_sizes, int n_in,
                              void* d_out, int out_size) {
    const float* x   = (const float*)d_in[0];
    const float* wts = (const float*)d_in[1];
    int nx = in_sizes[0];
    if (n_in >= 2 && in_sizes[0] == 72 && in_sizes[1] != 72) {
        wts = (const float*)d_in[0];
        x   = (const float*)d_in[1];
        nx  = in_sizes[1];
    }
    int B = nx / 4;              // 262144
    int quarter = B / 4;         // 4 elems/thread
    int grid = (quarter + 127) / 128;

    prep_kernel<<<1, 512>>>(wts);

    // PDL launch: qmain's prologue overlaps prep; cudaGridDependencySynchronize
    // in the kernel gates the g_U read on prep completion.
    cudaLaunchConfig_t cfg = {};
    cfg.gridDim  = dim3((unsigned)grid, 1, 1);
    cfg.blockDim = dim3(128, 1, 1);
    cfg.dynamicSmemBytes = 0;
    cfg.stream = 0;
    cudaLaunchAttribute attrs[1];
    attrs[0].id = cudaLaunchAttributeProgrammaticStreamSerialization;
    attrs[0].val.programmaticStreamSerializationAllowed = 1;
    cfg.attrs = attrs;
    cfg.numAttrs = 1;
    cudaLaunchKernelEx(&cfg, qmain_kernel, (const float4*)x, (float4*)d_out, quarter);
}